// round 3
// baseline (speedup 1.0000x reference)
#include <cuda_runtime.h>

// Inputs (metadata order):
// 0: y (B,4N) f32 | 1: Ic (B,) | 2: C (N,) | 3: g_Na | 4: E_Na | 5: g_K | 6: E_K
// 7: g_L | 8: E_L | 9: m_inf | 10: tau_m | 11: h_inf | 12: tau_h | 13: n_inf
// 14: tau_n | 15: g_C (N,N)
// Output: ydot (B,4N) followed by J (B,4N,4N), f32.

#define BATCH 256
#define NN    128   // N
#define E4    512   // 4*N

__device__ float g_S;  // sum over all (i,j) of g_C[i,j] / C[j]

// ---------------------------------------------------------------------------
// Kernel 1: ydot.  grid = BATCH blocks, 128 threads (one per neuron).
// Block 0 additionally computes g_S (reduction of gC * invC) — the data is
// already resident (gC rows in L2, invC in smem), so this replaces the old
// 13.7us single-block s_kernel at ~zero cost.
// ---------------------------------------------------------------------------
__global__ void ydot_kernel(
    const float* __restrict__ y, const float* __restrict__ Ic,
    const float* __restrict__ C,
    const float* __restrict__ gNa, const float* __restrict__ ENa,
    const float* __restrict__ gK,  const float* __restrict__ EK,
    const float* __restrict__ gL,  const float* __restrict__ EL,
    const float* __restrict__ minf, const float* __restrict__ taum,
    const float* __restrict__ hinf, const float* __restrict__ tauh,
    const float* __restrict__ ninf, const float* __restrict__ taun,
    const float* __restrict__ gC,
    float* __restrict__ out)
{
    __shared__ float Vs[NN];
    __shared__ float Wj[NN];   // invC[j]
    __shared__ float red[4];

    int b = blockIdx.x;
    int i = threadIdx.x;

    float4 y4 = reinterpret_cast<const float4*>(y)[b * NN + i];
    float V = y4.x, m = y4.y, h = y4.z, n = y4.w;
    float invCi = 1.0f / C[i];
    Vs[i] = V;
    Wj[i] = invCi;
    __syncthreads();

    // coupling: sum_j gC[i,j] * invC[j] * (V_i - V_j)
    float acc = 0.0f;
    const float* gCrow = gC + i * NN;
    #pragma unroll 8
    for (int j = 0; j < NN; j++)
        acc += gCrow[j] * Wj[j] * (V - Vs[j]);

    float m2 = m * m, m3 = m2 * m;
    float n2 = n * n, n4 = n2 * n2;
    float Vdot = invCi * (-gNa[i] * m3 * h * (V - ENa[i])
                          - gK[i] * n4 * (V - EK[i])
                          - gL[i] * (V - EL[i])
                          + Ic[b]) + acc;
    float mdot = (minf[i] - m) / taum[i];
    float hdot = (hinf[i] - h) / tauh[i];
    float ndot = (ninf[i] - n) / taun[i];

    float4 o;
    o.x = Vdot; o.y = mdot; o.z = hdot; o.w = ndot;
    reinterpret_cast<float4*>(out)[b * NN + i] = o;

    // ---- block 0 only: S = sum_{i,j} gC[i,j] * invC[j] ----
    if (b == 0) {
        float rs = 0.0f;
        #pragma unroll 8
        for (int j = 0; j < NN; j++)
            rs += gCrow[j] * Wj[j];
        #pragma unroll
        for (int o2 = 16; o2 > 0; o2 >>= 1)
            rs += __shfl_xor_sync(0xFFFFFFFFu, rs, o2);
        if ((i & 31) == 0) red[i >> 5] = rs;
        __syncthreads();
        if (i == 0)
            g_S = red[0] + red[1] + red[2] + red[3];
    }
}

// ---------------------------------------------------------------------------
// Kernel 2: fill J.  Each thread writes 4 consecutive float4 (64 B) covering
// columns 4*jq*4 .. 4*jq*4+15?  Layout: thread handles j in [4*jq, 4*jq+4),
// row r, batch b.  idx: jq = idx & 31; r = (idx>>5) & 511; b = idx >> 14.
// Total threads = 256*512*32 = 4,194,304.
// ---------------------------------------------------------------------------
__global__ void jfill_kernel(
    const float* __restrict__ y,
    const float* __restrict__ C,
    const float* __restrict__ gNa, const float* __restrict__ ENa,
    const float* __restrict__ gK,  const float* __restrict__ EK,
    const float* __restrict__ gL,
    const float* __restrict__ taum, const float* __restrict__ tauh,
    const float* __restrict__ taun,
    const float* __restrict__ gC,
    float* __restrict__ J)
{
    int idx = blockIdx.x * blockDim.x + threadIdx.x;
    int jq = idx & 31;            // j-quad: j = 4*jq + q, q in 0..3
    int r  = (idx >> 5) & (E4 - 1);
    int b  = idx >> 14;

    int rt = r & 3;               // warp-uniform (32 jq per row-group)
    int i  = r >> 2;

    float4 v0 = make_float4(0.f,0.f,0.f,0.f);
    float4 v1 = v0, v2 = v0, v3 = v0;

    if (rt == 0) {
        float4 gc4 = reinterpret_cast<const float4*>(gC + i * NN)[jq];
        float4 c4  = reinterpret_cast<const float4*>(C)[jq];
        v0.x = -gc4.x / c4.x;
        v1.x = -gc4.y / c4.y;
        v2.x = -gc4.z / c4.z;
        v3.x = -gc4.w / c4.w;
        if ((i >> 2) == jq) {
            int q = i & 3;
            float invCi = (q == 0) ? 1.0f/c4.x : (q == 1) ? 1.0f/c4.y
                        : (q == 2) ? 1.0f/c4.z : 1.0f/c4.w;
            float4 y4 = reinterpret_cast<const float4*>(y)[b * NN + i];
            float V = y4.x, m = y4.y, h = y4.z, n = y4.w;
            float m2 = m * m, m3 = m2 * m;
            float n2 = n * n, n3 = n2 * n, n4 = n3 * n;
            float ga = gNa[i], gk = gK[i];
            float dNa = V - ENa[i], dK = V - EK[i];
            float dx = g_S + invCi * (-gL[i] - ga * h * m3 - gk * n4);
            float dy = -invCi * (3.0f * ga * h * m2 * dNa);
            float dz = -invCi * (ga * m3 * dNa);
            float dw = -invCi * (4.0f * gk * n3 * dK);
            if      (q == 0) { v0.x += dx; v0.y = dy; v0.z = dz; v0.w = dw; }
            else if (q == 1) { v1.x += dx; v1.y = dy; v1.z = dz; v1.w = dw; }
            else if (q == 2) { v2.x += dx; v2.y = dy; v2.z = dz; v2.w = dw; }
            else             { v3.x += dx; v3.y = dy; v3.z = dz; v3.w = dw; }
        }
    } else if ((i >> 2) == jq) {
        int q = i & 3;
        float t = (rt == 1) ? taum[i] : (rt == 2) ? tauh[i] : taun[i];
        float val = -1.0f / t;
        // nonzero goes to component rt of the quad q
        float* vq = (q == 0) ? &v0.x : (q == 1) ? &v1.x : (q == 2) ? &v2.x : &v3.x;
        vq[rt] = val;
    }

    float4* out = reinterpret_cast<float4*>(J) + (size_t)idx * 4;
    out[0] = v0; out[1] = v1; out[2] = v2; out[3] = v3;
}

// ---------------------------------------------------------------------------
extern "C" void kernel_launch(void* const* d_in, const int* in_sizes, int n_in,
                              void* d_out, int out_size) {
    const float* y    = (const float*)d_in[0];
    const float* Ic   = (const float*)d_in[1];
    const float* C    = (const float*)d_in[2];
    const float* gNa  = (const float*)d_in[3];
    const float* ENa  = (const float*)d_in[4];
    const float* gK   = (const float*)d_in[5];
    const float* EK   = (const float*)d_in[6];
    const float* gL   = (const float*)d_in[7];
    const float* EL   = (const float*)d_in[8];
    const float* minf = (const float*)d_in[9];
    const float* taum = (const float*)d_in[10];
    const float* hinf = (const float*)d_in[11];
    const float* tauh = (const float*)d_in[12];
    const float* ninf = (const float*)d_in[13];
    const float* taun = (const float*)d_in[14];
    const float* gC   = (const float*)d_in[15];

    float* out_ydot = (float*)d_out;
    float* out_J    = out_ydot + BATCH * E4;

    ydot_kernel<<<BATCH, NN>>>(y, Ic, C, gNa, ENa, gK, EK, gL, EL,
                               minf, taum, hinf, tauh, ninf, taun, gC, out_ydot);
    const int nthreads = BATCH * E4 * 32;   // 4,194,304
    jfill_kernel<<<nthreads / 256, 256>>>(y, C, gNa, ENa, gK, EK, gL,
                                          taum, tauh, taun, gC, out_J);
}

// round 4
// speedup vs baseline: 1.3950x; 1.3950x over previous
#include <cuda_runtime.h>

// Inputs (metadata order):
// 0: y (B,4N) f32 | 1: Ic (B,) | 2: C (N,) | 3: g_Na | 4: E_Na | 5: g_K | 6: E_K
// 7: g_L | 8: E_L | 9: m_inf | 10: tau_m | 11: h_inf | 12: tau_h | 13: n_inf
// 14: tau_n | 15: g_C (N,N)
// Output: ydot (B,4N) followed by J (B,4N,4N), f32.

#define BATCH 256
#define NN    128   // N
#define E4    512   // 4*N

__device__ float g_S;  // sum over all (i,j) of g_C[i,j] / C[j]

// ---------------------------------------------------------------------------
// Kernel 1: ydot.  grid = BATCH blocks, 128 threads (one per neuron).
// Block 0 additionally computes g_S (reduction of gC * invC).
// ---------------------------------------------------------------------------
__global__ void ydot_kernel(
    const float* __restrict__ y, const float* __restrict__ Ic,
    const float* __restrict__ C,
    const float* __restrict__ gNa, const float* __restrict__ ENa,
    const float* __restrict__ gK,  const float* __restrict__ EK,
    const float* __restrict__ gL,  const float* __restrict__ EL,
    const float* __restrict__ minf, const float* __restrict__ taum,
    const float* __restrict__ hinf, const float* __restrict__ tauh,
    const float* __restrict__ ninf, const float* __restrict__ taun,
    const float* __restrict__ gC,
    float* __restrict__ out)
{
    __shared__ float Vs[NN];
    __shared__ float Wj[NN];   // invC[j]
    __shared__ float red[4];

    int b = blockIdx.x;
    int i = threadIdx.x;

    float4 y4 = reinterpret_cast<const float4*>(y)[b * NN + i];
    float V = y4.x, m = y4.y, h = y4.z, n = y4.w;
    float invCi = 1.0f / C[i];
    Vs[i] = V;
    Wj[i] = invCi;
    __syncthreads();

    // coupling: sum_j gC[i,j] * invC[j] * (V_i - V_j)
    float acc = 0.0f;
    const float* gCrow = gC + i * NN;
    #pragma unroll 8
    for (int j = 0; j < NN; j++)
        acc += gCrow[j] * Wj[j] * (V - Vs[j]);

    float m2 = m * m, m3 = m2 * m;
    float n2 = n * n, n4 = n2 * n2;
    float Vdot = invCi * (-gNa[i] * m3 * h * (V - ENa[i])
                          - gK[i] * n4 * (V - EK[i])
                          - gL[i] * (V - EL[i])
                          + Ic[b]) + acc;
    float mdot = (minf[i] - m) / taum[i];
    float hdot = (hinf[i] - h) / tauh[i];
    float ndot = (ninf[i] - n) / taun[i];

    float4 o;
    o.x = Vdot; o.y = mdot; o.z = hdot; o.w = ndot;
    reinterpret_cast<float4*>(out)[b * NN + i] = o;

    // ---- block 0 only: S = sum_{i,j} gC[i,j] * invC[j] ----
    if (b == 0) {
        float rs = 0.0f;
        #pragma unroll 8
        for (int j = 0; j < NN; j++)
            rs += gCrow[j] * Wj[j];
        #pragma unroll
        for (int o2 = 16; o2 > 0; o2 >>= 1)
            rs += __shfl_xor_sync(0xFFFFFFFFu, rs, o2);
        if ((i & 31) == 0) red[i >> 5] = rs;
        __syncthreads();
        if (i == 0)
            g_S = red[0] + red[1] + red[2] + red[3];
    }
}

// ---------------------------------------------------------------------------
// J value for flat float4-index idx (covers columns 4j..4j+3 of row r, batch b).
// idx layout: j = idx & 127; r = (idx >> 7) & 511; b = idx >> 16.
// ---------------------------------------------------------------------------
__device__ __forceinline__ float4 jval(
    int idx,
    const float* __restrict__ y,
    const float* __restrict__ C,
    const float* __restrict__ gNa, const float* __restrict__ ENa,
    const float* __restrict__ gK,  const float* __restrict__ EK,
    const float* __restrict__ gL,
    const float* __restrict__ taum, const float* __restrict__ tauh,
    const float* __restrict__ taun,
    const float* __restrict__ gC)
{
    int j = idx & (NN - 1);
    int r = (idx >> 7) & (E4 - 1);
    int b = idx >> 16;

    int rt = r & 3;        // warp-uniform (128 j's per row)
    int i  = r >> 2;

    float4 v = make_float4(0.f, 0.f, 0.f, 0.f);

    if (rt == 0) {
        float invCj = 1.0f / C[j];
        float gc = gC[i * NN + j];
        v.x = -gc * invCj;
        if (i == j) {
            float4 y4 = reinterpret_cast<const float4*>(y)[b * NN + i];
            float V = y4.x, m = y4.y, h = y4.z, n = y4.w;
            float invCi = invCj;  // i == j
            float m2 = m * m, m3 = m2 * m;
            float n2 = n * n, n3 = n2 * n, n4 = n3 * n;
            float ga = gNa[i], gk = gK[i];
            float dNa = V - ENa[i], dK = V - EK[i];
            v.x += g_S + invCi * (-gL[i] - ga * h * m3 - gk * n4);
            v.y = -invCi * (3.0f * ga * h * m2 * dNa);
            v.z = -invCi * (ga * m3 * dNa);
            v.w = -invCi * (4.0f * gk * n3 * dK);
        }
    } else if (i == j) {
        float t = (rt == 1) ? taum[i] : (rt == 2) ? tauh[i] : taun[i];
        float val = -1.0f / t;
        if (rt == 1) v.y = val;
        else if (rt == 2) v.z = val;
        else v.w = val;
    }
    return v;
}

// ---------------------------------------------------------------------------
// Kernel 2: fill J.  Each thread writes 2 float4s, both warp-coalesced
// (strided by blockDim within the block's tile of 512 float4s).
// total float4 = 256*512*128 = 16,777,216 -> 32768 blocks of 256 threads.
// ---------------------------------------------------------------------------
__global__ void jfill_kernel(
    const float* __restrict__ y,
    const float* __restrict__ C,
    const float* __restrict__ gNa, const float* __restrict__ ENa,
    const float* __restrict__ gK,  const float* __restrict__ EK,
    const float* __restrict__ gL,
    const float* __restrict__ taum, const float* __restrict__ tauh,
    const float* __restrict__ taun,
    const float* __restrict__ gC,
    float* __restrict__ J)
{
    int base = blockIdx.x * 512 + threadIdx.x;
    int idx0 = base;
    int idx1 = base + 256;

    float4 v0 = jval(idx0, y, C, gNa, ENa, gK, EK, gL, taum, tauh, taun, gC);
    float4 v1 = jval(idx1, y, C, gNa, ENa, gK, EK, gL, taum, tauh, taun, gC);

    float4* out = reinterpret_cast<float4*>(J);
    out[idx0] = v0;
    out[idx1] = v1;
}

// ---------------------------------------------------------------------------
extern "C" void kernel_launch(void* const* d_in, const int* in_sizes, int n_in,
                              void* d_out, int out_size) {
    const float* y    = (const float*)d_in[0];
    const float* Ic   = (const float*)d_in[1];
    const float* C    = (const float*)d_in[2];
    const float* gNa  = (const float*)d_in[3];
    const float* ENa  = (const float*)d_in[4];
    const float* gK   = (const float*)d_in[5];
    const float* EK   = (const float*)d_in[6];
    const float* gL   = (const float*)d_in[7];
    const float* EL   = (const float*)d_in[8];
    const float* minf = (const float*)d_in[9];
    const float* taum = (const float*)d_in[10];
    const float* hinf = (const float*)d_in[11];
    const float* tauh = (const float*)d_in[12];
    const float* ninf = (const float*)d_in[13];
    const float* taun = (const float*)d_in[14];
    const float* gC   = (const float*)d_in[15];

    float* out_ydot = (float*)d_out;
    float* out_J    = out_ydot + BATCH * E4;

    ydot_kernel<<<BATCH, NN>>>(y, Ic, C, gNa, ENa, gK, EK, gL, EL,
                               minf, taum, hinf, tauh, ninf, taun, gC, out_ydot);
    const int total4 = BATCH * E4 * NN;   // 16,777,216 float4
    jfill_kernel<<<total4 / 512, 256>>>(y, C, gNa, ENa, gK, EK, gL,
                                        taum, tauh, taun, gC, out_J);
}

// round 5
// speedup vs baseline: 1.6105x; 1.1544x over previous
#include <cuda_runtime.h>

// Inputs (metadata order):
// 0: y (B,4N) f32 | 1: Ic (B,) | 2: C (N,) | 3: g_Na | 4: E_Na | 5: g_K | 6: E_K
// 7: g_L | 8: E_L | 9: m_inf | 10: tau_m | 11: h_inf | 12: tau_h | 13: n_inf
// 14: tau_n | 15: g_C (N,N)
// Output: ydot (B,4N) followed by J (B,4N,4N), f32.

#define BATCH 256
#define NN    128   // N
#define E4    512   // 4*N

// per-(b,i) diagonal Jacobian 4-tuple: (JVV_diag_part(+S), JVm, JVh, JVn)
__device__ float4 g_diag[BATCH * NN];

// ---------------------------------------------------------------------------
// Kernel 1: ydot + diagonal precompute.  grid = BATCH blocks, 128 threads.
// Every block computes S = sum_{i,j} gC[i,j]*invC[j] for free: the coupling
// loop already forms gC[i,j]*invC[j]; we just also accumulate its plain sum
// and block-reduce.  Fully deterministic (fixed reduction tree).
// ---------------------------------------------------------------------------
__global__ void ydot_kernel(
    const float* __restrict__ y, const float* __restrict__ Ic,
    const float* __restrict__ C,
    const float* __restrict__ gNa, const float* __restrict__ ENa,
    const float* __restrict__ gK,  const float* __restrict__ EK,
    const float* __restrict__ gL,  const float* __restrict__ EL,
    const float* __restrict__ minf, const float* __restrict__ taum,
    const float* __restrict__ hinf, const float* __restrict__ tauh,
    const float* __restrict__ ninf, const float* __restrict__ taun,
    const float* __restrict__ gC,
    float* __restrict__ out)
{
    __shared__ float Vs[NN];
    __shared__ float Wj[NN];   // invC[j]
    __shared__ float red[4];

    int b = blockIdx.x;
    int i = threadIdx.x;

    float4 y4 = reinterpret_cast<const float4*>(y)[b * NN + i];
    float V = y4.x, m = y4.y, h = y4.z, n = y4.w;
    float invCi = 1.0f / C[i];
    Vs[i] = V;
    Wj[i] = invCi;
    __syncthreads();

    // coupling + free row-sum for S
    float acc = 0.0f;
    float rs  = 0.0f;
    const float* gCrow = gC + i * NN;
    #pragma unroll 8
    for (int j = 0; j < NN; j++) {
        float gcw = gCrow[j] * Wj[j];
        acc += gcw * (V - Vs[j]);
        rs  += gcw;
    }

    // block-reduce rs -> S (deterministic tree), broadcast through smem
    float t = rs;
    #pragma unroll
    for (int o2 = 16; o2 > 0; o2 >>= 1)
        t += __shfl_xor_sync(0xFFFFFFFFu, t, o2);
    if ((i & 31) == 0) red[i >> 5] = t;
    __syncthreads();
    float S = red[0] + red[1] + red[2] + red[3];

    float m2 = m * m, m3 = m2 * m;
    float n2 = n * n, n3 = n2 * n, n4 = n3 * n;
    float ga = gNa[i], gk = gK[i], gl = gL[i];
    float dNa = V - ENa[i], dK = V - EK[i];

    float Vdot = invCi * (-ga * m3 * h * dNa
                          - gk * n4 * dK
                          - gl * (V - EL[i])
                          + Ic[b]) + acc;
    float mdot = (minf[i] - m) / taum[i];
    float hdot = (hinf[i] - h) / tauh[i];
    float ndot = (ninf[i] - n) / taun[i];

    float4 o;
    o.x = Vdot; o.y = mdot; o.z = hdot; o.w = ndot;
    reinterpret_cast<float4*>(out)[b * NN + i] = o;

    // diagonal Jacobian tuple for jfill
    float4 d;
    d.x = S + invCi * (-gl - ga * h * m3 - gk * n4);
    d.y = -invCi * (3.0f * ga * h * m2 * dNa);
    d.z = -invCi * (ga * m3 * dNa);
    d.w = -invCi * (4.0f * gk * n3 * dK);
    g_diag[b * NN + i] = d;
}

// ---------------------------------------------------------------------------
// Kernel 2: fill J.  Each thread writes 4 float4s, all warp-coalesced
// (interleaved at stride 256 within the block's tile of 1024 float4s).
// float4-idx layout: j = idx & 127; r = (idx >> 7) & 511; b = idx >> 16.
// j is identical for all 4 stores of a thread (stride 256 == 0 mod 128).
// total float4 = 16,777,216 -> 16384 blocks of 256 threads.
// ---------------------------------------------------------------------------
__global__ void jfill_kernel(
    const float* __restrict__ C,
    const float* __restrict__ taum, const float* __restrict__ tauh,
    const float* __restrict__ taun,
    const float* __restrict__ gC,
    float* __restrict__ J)
{
    int base = blockIdx.x * 1024 + threadIdx.x;
    int j = base & (NN - 1);
    float invCj = 1.0f / C[j];

    float4* out = reinterpret_cast<float4*>(J);

    #pragma unroll
    for (int k = 0; k < 4; k++) {
        int idx = base + k * 256;
        int r = (idx >> 7) & (E4 - 1);
        int b = idx >> 16;
        int rt = r & 3;      // warp-uniform
        int i  = r >> 2;

        float4 v = make_float4(0.f, 0.f, 0.f, 0.f);

        if (rt == 0) {
            v.x = -gC[i * NN + j] * invCj;
            if (i == j) {
                float4 d = g_diag[b * NN + i];
                v.x += d.x; v.y = d.y; v.z = d.z; v.w = d.w;
            }
        } else if (i == j) {
            float tt = (rt == 1) ? taum[i] : (rt == 2) ? tauh[i] : taun[i];
            float val = -1.0f / tt;
            if (rt == 1) v.y = val;
            else if (rt == 2) v.z = val;
            else v.w = val;
        }

        out[idx] = v;
    }
}

// ---------------------------------------------------------------------------
extern "C" void kernel_launch(void* const* d_in, const int* in_sizes, int n_in,
                              void* d_out, int out_size) {
    const float* y    = (const float*)d_in[0];
    const float* Ic   = (const float*)d_in[1];
    const float* C    = (const float*)d_in[2];
    const float* gNa  = (const float*)d_in[3];
    const float* ENa  = (const float*)d_in[4];
    const float* gK   = (const float*)d_in[5];
    const float* EK   = (const float*)d_in[6];
    const float* gL   = (const float*)d_in[7];
    const float* EL   = (const float*)d_in[8];
    const float* minf = (const float*)d_in[9];
    const float* taum = (const float*)d_in[10];
    const float* hinf = (const float*)d_in[11];
    const float* tauh = (const float*)d_in[12];
    const float* ninf = (const float*)d_in[13];
    const float* taun = (const float*)d_in[14];
    const float* gC   = (const float*)d_in[15];

    float* out_ydot = (float*)d_out;
    float* out_J    = out_ydot + BATCH * E4;

    ydot_kernel<<<BATCH, NN>>>(y, Ic, C, gNa, ENa, gK, EK, gL, EL,
                               minf, taum, hinf, tauh, ninf, taun, gC, out_ydot);
    const int total4 = BATCH * E4 * NN;   // 16,777,216 float4
    jfill_kernel<<<total4 / 1024, 256>>>(C, taum, tauh, taun, gC, out_J);
}

// round 6
// speedup vs baseline: 1.9393x; 1.2041x over previous
#include <cuda_runtime.h>

// Inputs (metadata order):
// 0: y (B,4N) f32 | 1: Ic (B,) | 2: C (N,) | 3: g_Na | 4: E_Na | 5: g_K | 6: E_K
// 7: g_L | 8: E_L | 9: m_inf | 10: tau_m | 11: h_inf | 12: tau_h | 13: n_inf
// 14: tau_n | 15: g_C (N,N)
// Output: ydot (B,4N) followed by J (B,4N,4N), f32.

#define BATCH 256
#define NN    128   // N
#define E4    512   // 4*N

// per-(b,i) diagonal Jacobian 4-tuple: (JVV_diag_part(+S), JVm, JVh, JVn)
__device__ float4 g_diag[BATCH * NN];

// ---------------------------------------------------------------------------
// Kernel 1: ydot + diagonal precompute.  grid = BATCH blocks, 128 threads.
// gC is staged through smem in 128x32 column tiles so ALL global reads are
// warp-coalesced (previous version had 8x sector inflation: ~20us -> ~5us).
// acc_i = V_i * rs_i - dot(g_i, invC.*V);   rs_i = dot(g_i, invC)
// S = sum_i rs_i (deterministic block reduce, identical in every block).
// ---------------------------------------------------------------------------
__global__ void ydot_kernel(
    const float* __restrict__ y, const float* __restrict__ Ic,
    const float* __restrict__ C,
    const float* __restrict__ gNa, const float* __restrict__ ENa,
    const float* __restrict__ gK,  const float* __restrict__ EK,
    const float* __restrict__ gL,  const float* __restrict__ EL,
    const float* __restrict__ minf, const float* __restrict__ taum,
    const float* __restrict__ hinf, const float* __restrict__ tauh,
    const float* __restrict__ ninf, const float* __restrict__ taun,
    const float* __restrict__ gC,
    float* __restrict__ out)
{
    __shared__ float Gt[NN][33];   // padded tile: conflict-free rows & cols
    __shared__ float Wj[NN];       // invC[j]
    __shared__ float WV[NN];       // invC[j] * V[j]
    __shared__ float red[4];

    int b = blockIdx.x;
    int i = threadIdx.x;
    int lane = i & 31;
    int w    = i >> 5;

    float4 y4 = reinterpret_cast<const float4*>(y)[b * NN + i];
    float V = y4.x, m = y4.y, h = y4.z, n = y4.w;
    float invCi = 1.0f / C[i];
    Wj[i] = invCi;
    WV[i] = invCi * V;
    __syncthreads();

    float rs = 0.0f;   // sum_j g[i][j] * invC[j]
    float gv = 0.0f;   // sum_j g[i][j] * invC[j] * V[j]

    #pragma unroll
    for (int t = 0; t < 4; t++) {
        // load columns [32t, 32t+32) of gC, coalesced (lane = column)
        #pragma unroll 8
        for (int k = 0; k < 32; k++) {
            int row = k * 4 + w;
            Gt[row][lane] = gC[row * NN + t * 32 + lane];
        }
        __syncthreads();

        #pragma unroll 8
        for (int jj = 0; jj < 32; jj++) {
            float g = Gt[i][jj];
            int j = t * 32 + jj;
            rs += g * Wj[j];
            gv += g * WV[j];
        }
        __syncthreads();
    }

    float acc = V * rs - gv;

    // block-reduce rs -> S (deterministic tree), broadcast through smem
    float tr = rs;
    #pragma unroll
    for (int o2 = 16; o2 > 0; o2 >>= 1)
        tr += __shfl_xor_sync(0xFFFFFFFFu, tr, o2);
    if (lane == 0) red[w] = tr;
    __syncthreads();
    float S = red[0] + red[1] + red[2] + red[3];

    float m2 = m * m, m3 = m2 * m;
    float n2 = n * n, n3 = n2 * n, n4 = n3 * n;
    float ga = gNa[i], gk = gK[i], gl = gL[i];
    float dNa = V - ENa[i], dK = V - EK[i];

    float Vdot = invCi * (-ga * m3 * h * dNa
                          - gk * n4 * dK
                          - gl * (V - EL[i])
                          + Ic[b]) + acc;
    float mdot = (minf[i] - m) / taum[i];
    float hdot = (hinf[i] - h) / tauh[i];
    float ndot = (ninf[i] - n) / taun[i];

    float4 o;
    o.x = Vdot; o.y = mdot; o.z = hdot; o.w = ndot;
    reinterpret_cast<float4*>(out)[b * NN + i] = o;

    // diagonal Jacobian tuple for jfill
    float4 d;
    d.x = S + invCi * (-gl - ga * h * m3 - gk * n4);
    d.y = -invCi * (3.0f * ga * h * m2 * dNa);
    d.z = -invCi * (ga * m3 * dNa);
    d.w = -invCi * (4.0f * gk * n3 * dK);
    g_diag[b * NN + i] = d;
}

// ---------------------------------------------------------------------------
// Kernel 2: fill J (unchanged from R5 — measured at its store floor).
// Each thread writes 4 float4s, all warp-coalesced (stride-256 interleave
// within the block's tile of 1024 float4s).
// float4-idx layout: j = idx & 127; r = (idx >> 7) & 511; b = idx >> 16.
// ---------------------------------------------------------------------------
__global__ void jfill_kernel(
    const float* __restrict__ C,
    const float* __restrict__ taum, const float* __restrict__ tauh,
    const float* __restrict__ taun,
    const float* __restrict__ gC,
    float* __restrict__ J)
{
    int base = blockIdx.x * 1024 + threadIdx.x;
    int j = base & (NN - 1);
    float invCj = 1.0f / C[j];

    float4* out = reinterpret_cast<float4*>(J);

    #pragma unroll
    for (int k = 0; k < 4; k++) {
        int idx = base + k * 256;
        int r = (idx >> 7) & (E4 - 1);
        int b = idx >> 16;
        int rt = r & 3;      // warp-uniform
        int i  = r >> 2;

        float4 v = make_float4(0.f, 0.f, 0.f, 0.f);

        if (rt == 0) {
            v.x = -gC[i * NN + j] * invCj;
            if (i == j) {
                float4 d = g_diag[b * NN + i];
                v.x += d.x; v.y = d.y; v.z = d.z; v.w = d.w;
            }
        } else if (i == j) {
            float tt = (rt == 1) ? taum[i] : (rt == 2) ? tauh[i] : taun[i];
            float val = -1.0f / tt;
            if (rt == 1) v.y = val;
            else if (rt == 2) v.z = val;
            else v.w = val;
        }

        out[idx] = v;
    }
}

// ---------------------------------------------------------------------------
extern "C" void kernel_launch(void* const* d_in, const int* in_sizes, int n_in,
                              void* d_out, int out_size) {
    const float* y    = (const float*)d_in[0];
    const float* Ic   = (const float*)d_in[1];
    const float* C    = (const float*)d_in[2];
    const float* gNa  = (const float*)d_in[3];
    const float* ENa  = (const float*)d_in[4];
    const float* gK   = (const float*)d_in[5];
    const float* EK   = (const float*)d_in[6];
    const float* gL   = (const float*)d_in[7];
    const float* EL   = (const float*)d_in[8];
    const float* minf = (const float*)d_in[9];
    const float* taum = (const float*)d_in[10];
    const float* hinf = (const float*)d_in[11];
    const float* tauh = (const float*)d_in[12];
    const float* ninf = (const float*)d_in[13];
    const float* taun = (const float*)d_in[14];
    const float* gC   = (const float*)d_in[15];

    float* out_ydot = (float*)d_out;
    float* out_J    = out_ydot + BATCH * E4;

    ydot_kernel<<<BATCH, NN>>>(y, Ic, C, gNa, ENa, gK, EK, gL, EL,
                               minf, taum, hinf, tauh, ninf, taun, gC, out_ydot);
    const int total4 = BATCH * E4 * NN;   // 16,777,216 float4
    jfill_kernel<<<total4 / 1024, 256>>>(C, taum, tauh, taun, gC, out_J);
}

// round 8
// speedup vs baseline: 2.0674x; 1.0661x over previous
#include <cuda_runtime.h>

// Inputs (metadata order):
// 0: y (B,4N) f32 | 1: Ic (B,) | 2: C (N,) | 3: g_Na | 4: E_Na | 5: g_K | 6: E_K
// 7: g_L | 8: E_L | 9: m_inf | 10: tau_m | 11: h_inf | 12: tau_h | 13: n_inf
// 14: tau_n | 15: g_C (N,N)
// Output: ydot (B,4N) followed by J (B,4N,4N), f32.

#define BATCH 256
#define NN    128   // N
#define E4    512   // 4*N
#define BPB   4     // batches per ydot block

// per-(b,i) diagonal Jacobian 4-tuple: (JVV_diag_part(+S), JVm, JVh, JVn)
__device__ float4 g_diag[BATCH * NN];

// ---------------------------------------------------------------------------
// Kernel 1: ydot + diagonal precompute.  grid = BATCH/BPB blocks, 128 threads.
// Each block processes BPB batches, staging each gC column-tile ONCE and
// reusing it for all BPB batches (4x less gC traffic than one-batch blocks).
// rs_i = dot(g_i, invC) is batch-independent -> computed once, S reduced once.
// ---------------------------------------------------------------------------
__global__ void ydot_kernel(
    const float* __restrict__ y, const float* __restrict__ Ic,
    const float* __restrict__ C,
    const float* __restrict__ gNa, const float* __restrict__ ENa,
    const float* __restrict__ gK,  const float* __restrict__ EK,
    const float* __restrict__ gL,  const float* __restrict__ EL,
    const float* __restrict__ minf, const float* __restrict__ taum,
    const float* __restrict__ hinf, const float* __restrict__ tauh,
    const float* __restrict__ ninf, const float* __restrict__ taun,
    const float* __restrict__ gC,
    float* __restrict__ out)
{
    __shared__ float Gt[NN][33];       // padded column tile
    __shared__ float Wj[NN];           // invC[j]
    __shared__ float WVs[BPB][NN];     // invC[j] * V_b[j]
    __shared__ float red[4];

    int b0 = blockIdx.x * BPB;
    int i  = threadIdx.x;
    int lane = i & 31;
    int w    = i >> 5;

    float invCi = 1.0f / C[i];
    Wj[i] = invCi;

    float V[BPB], m[BPB], h[BPB], n[BPB];
    #pragma unroll
    for (int bb = 0; bb < BPB; bb++) {
        float4 y4 = reinterpret_cast<const float4*>(y)[(b0 + bb) * NN + i];
        V[bb] = y4.x; m[bb] = y4.y; h[bb] = y4.z; n[bb] = y4.w;
        WVs[bb][i] = invCi * y4.x;
    }
    __syncthreads();

    float rs = 0.0f;                   // sum_j g[i][j] * invC[j]  (batch-indep)
    float gv[BPB] = {0.f, 0.f, 0.f, 0.f};

    #pragma unroll
    for (int t = 0; t < 4; t++) {
        // load columns [32t, 32t+32) of gC, coalesced (lane = column)
        #pragma unroll 8
        for (int k = 0; k < 32; k++) {
            int row = k * 4 + w;
            Gt[row][lane] = gC[row * NN + t * 32 + lane];
        }
        __syncthreads();

        #pragma unroll 4
        for (int jj = 0; jj < 32; jj++) {
            float g = Gt[i][jj];
            int j = t * 32 + jj;
            rs += g * Wj[j];
            #pragma unroll
            for (int bb = 0; bb < BPB; bb++)
                gv[bb] += g * WVs[bb][j];
        }
        __syncthreads();
    }

    // block-reduce rs -> S (deterministic tree), broadcast through smem
    float tr = rs;
    #pragma unroll
    for (int o2 = 16; o2 > 0; o2 >>= 1)
        tr += __shfl_xor_sync(0xFFFFFFFFu, tr, o2);
    if (lane == 0) red[w] = tr;
    __syncthreads();
    float S = red[0] + red[1] + red[2] + red[3];

    // per-i parameters loaded once, reused for all BPB batches
    float ga = gNa[i], gk = gK[i], gl = gL[i];
    float eNa = ENa[i], eK = EK[i], eL = EL[i];
    float mi = minf[i], hi = hinf[i], ni = ninf[i];
    float itm = 1.0f / taum[i], ith = 1.0f / tauh[i], itn = 1.0f / taun[i];

    #pragma unroll
    for (int bb = 0; bb < BPB; bb++) {
        float Vb = V[bb], mb = m[bb], hb = h[bb], nb = n[bb];
        float acc = Vb * rs - gv[bb];
        float m2 = mb * mb, m3 = m2 * mb;
        float n2 = nb * nb, n3 = n2 * nb, n4 = n3 * nb;
        float dNa = Vb - eNa, dK = Vb - eK;

        float Vdot = invCi * (-ga * m3 * hb * dNa
                              - gk * n4 * dK
                              - gl * (Vb - eL)
                              + Ic[b0 + bb]) + acc;
        float4 o;
        o.x = Vdot;
        o.y = (mi - mb) * itm;
        o.z = (hi - hb) * ith;
        o.w = (ni - nb) * itn;
        reinterpret_cast<float4*>(out)[(b0 + bb) * NN + i] = o;

        float4 d;
        d.x = S + invCi * (-gl - ga * hb * m3 - gk * n4);
        d.y = -invCi * (3.0f * ga * hb * m2 * dNa);
        d.z = -invCi * (ga * m3 * dNa);
        d.w = -invCi * (4.0f * gk * n3 * dK);
        g_diag[(b0 + bb) * NN + i] = d;
    }
}

// ---------------------------------------------------------------------------
// streaming 128-bit store (evict-first: J is write-once, 2x L2 capacity)
// ---------------------------------------------------------------------------
__device__ __forceinline__ void stg_cs(float4* p, float4 v) {
    asm volatile("st.global.cs.v4.f32 [%0], {%1, %2, %3, %4};"
                 :: "l"(p), "f"(v.x), "f"(v.y), "f"(v.z), "f"(v.w)
                 : "memory");
}

// ---------------------------------------------------------------------------
// Kernel 2: fill J.  Each thread writes 4 float4s, all warp-coalesced
// (stride-256 interleave within the block's tile of 1024 float4s).
// float4-idx layout: j = idx & 127; r = (idx >> 7) & 511; b = idx >> 16.
// ---------------------------------------------------------------------------
__global__ void jfill_kernel(
    const float* __restrict__ C,
    const float* __restrict__ taum, const float* __restrict__ tauh,
    const float* __restrict__ taun,
    const float* __restrict__ gC,
    float* __restrict__ J)
{
    int base = blockIdx.x * 1024 + threadIdx.x;
    int j = base & (NN - 1);
    float invCj = 1.0f / C[j];

    float4* out = reinterpret_cast<float4*>(J);

    #pragma unroll
    for (int k = 0; k < 4; k++) {
        int idx = base + k * 256;
        int r = (idx >> 7) & (E4 - 1);
        int b = idx >> 16;
        int rt = r & 3;      // warp-uniform
        int i  = r >> 2;

        float4 v = make_float4(0.f, 0.f, 0.f, 0.f);

        if (rt == 0) {
            v.x = -gC[i * NN + j] * invCj;
            if (i == j) {
                float4 d = g_diag[b * NN + i];
                v.x += d.x; v.y = d.y; v.z = d.z; v.w = d.w;
            }
        } else if (i == j) {
            float tt = (rt == 1) ? taum[i] : (rt == 2) ? tauh[i] : taun[i];
            float val = -1.0f / tt;
            if (rt == 1) v.y = val;
            else if (rt == 2) v.z = val;
            else v.w = val;
        }

        stg_cs(out + idx, v);
    }
}

// ---------------------------------------------------------------------------
extern "C" void kernel_launch(void* const* d_in, const int* in_sizes, int n_in,
                              void* d_out, int out_size) {
    const float* y    = (const float*)d_in[0];
    const float* Ic   = (const float*)d_in[1];
    const float* C    = (const float*)d_in[2];
    const float* gNa  = (const float*)d_in[3];
    const float* ENa  = (const float*)d_in[4];
    const float* gK   = (const float*)d_in[5];
    const float* EK   = (const float*)d_in[6];
    const float* gL   = (const float*)d_in[7];
    const float* EL   = (const float*)d_in[8];
    const float* minf = (const float*)d_in[9];
    const float* taum = (const float*)d_in[10];
    const float* hinf = (const float*)d_in[11];
    const float* tauh = (const float*)d_in[12];
    const float* ninf = (const float*)d_in[13];
    const float* taun = (const float*)d_in[14];
    const float* gC   = (const float*)d_in[15];

    float* out_ydot = (float*)d_out;
    float* out_J    = out_ydot + BATCH * E4;

    ydot_kernel<<<BATCH / BPB, NN>>>(y, Ic, C, gNa, ENa, gK, EK, gL, EL,
                                     minf, taum, hinf, tauh, ninf, taun, gC,
                                     out_ydot);
    const int total4 = BATCH * E4 * NN;   // 16,777,216 float4
    jfill_kernel<<<total4 / 1024, 256>>>(C, taum, tauh, taun, gC, out_J);
}